// round 8
// baseline (speedup 1.0000x reference)
#include <cuda_runtime.h>
#include <cstdint>

#define TT 64
#define CC 128
#define HD 32
#define NTHREADS 256

// Bank rules (lane = 4*gid + tig):
//  A loads  arr[(m0+gid)*S + k0+tig]   -> S ≡ 4 (mod 32)
//  B loads  arr[(n0+gid)*S + k0+tig]   -> S ≡ 4 (mod 32)
#define QSS 36     // q fp32 [64][36]            extent 32 ✓
#define KSS 36     // k tf32 [64][36]            extent 32 ✓
#define VTS 68     // vT tf32 [32][68] [d][seq]  extent 64 ✓
#define SCS 68     // scores fp32 [64][68]       extent 64 ✓

#define OFF_Q  0
#define OFF_K  (OFF_Q + TT * QSS)          // 2304
#define OFF_VT (OFF_K + TT * KSS)          // 4608
#define OFF_SC (OFF_VT + HD * VTS)         // 6784
#define SMEM_FLOATS (OFF_SC + TT * SCS)    // 11136 floats = 44544 B

__device__ __forceinline__ uint32_t f2tf(float f) {
    uint32_t u;
    asm("cvt.rna.tf32.f32 %0, %1;" : "=r"(u) : "f"(f));
    return u;
}
__device__ __forceinline__ void split_tf(float f, uint32_t& hi, uint32_t& lo) {
    hi = f2tf(f);
    lo = f2tf(f - __uint_as_float(hi));
}
__device__ __forceinline__ void mma_tf32(float c[4],
                                         uint32_t a0, uint32_t a1, uint32_t a2, uint32_t a3,
                                         uint32_t b0, uint32_t b1) {
    asm("mma.sync.aligned.m16n8k8.row.col.f32.tf32.tf32.f32 "
        "{%0,%1,%2,%3},{%4,%5,%6,%7},{%8,%9},{%0,%1,%2,%3};"
        : "+f"(c[0]), "+f"(c[1]), "+f"(c[2]), "+f"(c[3])
        : "r"(a0), "r"(a1), "r"(a2), "r"(a3), "r"(b0), "r"(b1));
}

__global__ __launch_bounds__(NTHREADS, 3)
void head_attn_kernel(const float* __restrict__ x,
                      const float* __restrict__ Wq,
                      const float* __restrict__ Wk,
                      const float* __restrict__ Wv,
                      float* __restrict__ out) {
    extern __shared__ float smem[];
    float*    qsm = smem + OFF_Q;
    uint32_t* ku  = reinterpret_cast<uint32_t*>(smem + OFF_K);   // k[seq][d] tf32
    uint32_t* vT  = reinterpret_cast<uint32_t*>(smem + OFF_VT);  // vT[d][seq] tf32
    float*    sc  = smem + OFF_SC;                               // scores/probs fp32

    const int tid  = threadIdx.x;
    const int warp = tid >> 5;
    const int lane = tid & 31;
    const int gid  = lane >> 2;   // 0..7
    const int tig  = lane & 3;    // 0..3
    const int b    = blockIdx.x;
    const float* xb = x + (size_t)b * (TT * CC);

    // ---------------- Phase 1: QKV via tf32 MMA, operands from GLOBAL ----------------
    // M=64, N=96, K=128. warp: m-tile = warp&3, n-tiles = 6*(warp>>2)+0..5.
    // A (x): fp32 from global, hi/lo split. B (W): fp32 from global, cvt.rna at use.
    {
        const int m0    = (warp & 3) * 16;
        const int nbase = (warp >> 2) * 48;

        float acc[6][4];
        #pragma unroll
        for (int j = 0; j < 6; j++)
            #pragma unroll
            for (int t = 0; t < 4; t++) acc[j][t] = 0.0f;

        // per-n-tile W base pointer (each 8-wide tile lies in one matrix)
        const float* wptr[6];
        #pragma unroll
        for (int j = 0; j < 6; j++) {
            int n0 = nbase + 8 * j;
            const float* m = (n0 < 32) ? Wq : (n0 < 64) ? Wk : Wv;
            wptr[j] = m + (n0 & 31) + gid;
        }
        const float* xr0 = xb + (m0 + gid)     * CC + tig;
        const float* xr1 = xb + (m0 + gid + 8) * CC + tig;

        for (int k0 = 0; k0 < CC; k0 += 8) {
            float a0 = __ldg(xr0 + k0);
            float a1 = __ldg(xr1 + k0);
            float a2 = __ldg(xr0 + k0 + 4);
            float a3 = __ldg(xr1 + k0 + 4);
            uint32_t h0, l0, h1, l1, h2, l2, h3, l3;
            split_tf(a0, h0, l0); split_tf(a1, h1, l1);
            split_tf(a2, h2, l2); split_tf(a3, h3, l3);
            const int ro0 = (k0 + tig) * HD;
            const int ro1 = (k0 + tig + 4) * HD;
            #pragma unroll
            for (int j = 0; j < 6; j++) {
                uint32_t b0 = f2tf(__ldg(wptr[j] + ro0));
                uint32_t b1 = f2tf(__ldg(wptr[j] + ro1));
                mma_tf32(acc[j], h0, h1, h2, h3, b0, b1);
                mma_tf32(acc[j], l0, l1, l2, l3, b0, b1);
            }
        }

        // scatter: n<32 -> q fp32 [seq][d]; 32..63 -> k tf32 [seq][d];
        //          >=64 -> vT tf32 [d][seq]
        #pragma unroll
        for (int j = 0; j < 6; j++) {
            int n0 = nbase + 8 * j;
            int c  = n0 + 2 * tig;
            #pragma unroll
            for (int half = 0; half < 2; half++) {
                int row = m0 + gid + 8 * half;
                float v0 = acc[j][2 * half];
                float v1 = acc[j][2 * half + 1];
                if (n0 < 32) {
                    qsm[row * QSS + c]     = v0;
                    qsm[row * QSS + c + 1] = v1;
                } else if (n0 < 64) {
                    ku[row * KSS + (c - 32)] = f2tf(v0);
                    ku[row * KSS + (c - 31)] = f2tf(v1);
                } else {
                    vT[(c - 64) * VTS + row] = f2tf(v0);
                    vT[(c - 63) * VTS + row] = f2tf(v1);
                }
            }
        }
    }
    __syncthreads();

    // ---------------- Phase 2: scores via tf32 MMA ----------------
    // M=64, N=64, K=32. warp: m-tile i=warp&3, n-tiles j=(warp>>2)+2t, j<=2i+1
    {
        const int i  = warp & 3;
        const int m0 = 16 * i;
        const int jb = warp >> 2;
        int jn[4], cnt = 0;
        #pragma unroll
        for (int t = 0; t < 4; t++) {
            int j = jb + 2 * t;
            if (j <= 2 * i + 1) jn[cnt++] = j;
        }

        float acc[4][4];
        #pragma unroll
        for (int t = 0; t < 4; t++)
            #pragma unroll
            for (int e = 0; e < 4; e++) acc[t][e] = 0.0f;

        for (int k0 = 0; k0 < HD; k0 += 8) {
            float a0 = qsm[(m0 + gid)     * QSS + k0 + tig];
            float a1 = qsm[(m0 + gid + 8) * QSS + k0 + tig];
            float a2 = qsm[(m0 + gid)     * QSS + k0 + tig + 4];
            float a3 = qsm[(m0 + gid + 8) * QSS + k0 + tig + 4];
            uint32_t h0, l0, h1, l1, h2, l2, h3, l3;
            split_tf(a0, h0, l0); split_tf(a1, h1, l1);
            split_tf(a2, h2, l2); split_tf(a3, h3, l3);
            for (int t = 0; t < cnt; t++) {
                int n0 = 8 * jn[t];
                uint32_t b0 = ku[(n0 + gid) * KSS + k0 + tig];
                uint32_t b1 = ku[(n0 + gid) * KSS + k0 + tig + 4];
                mma_tf32(acc[t], h0, h1, h2, h3, b0, b1);
                mma_tf32(acc[t], l0, l1, l2, l3, b0, b1);
            }
        }

        const float scale = 0.17677669529663687f;   // 1/sqrt(32)
        for (int t = 0; t < cnt; t++) {
            int n0 = 8 * jn[t];
            int c  = n0 + 2 * tig;
            #pragma unroll
            for (int half = 0; half < 2; half++) {
                int row = m0 + gid + 8 * half;
                sc[row * SCS + c]     = acc[t][2 * half]     * scale;
                sc[row * SCS + c + 1] = acc[t][2 * half + 1] * scale;
            }
        }
    }
    __syncthreads();

    // ---------------- Phase 3: causal softmax, one warp per row ----------------
    {
        for (int r = warp; r < TT; r += 8) {
            float* row = sc + r * SCS;
            bool v0 = (lane <= r);
            bool v1 = (lane + 32 <= r);
            float s0 = v0 ? row[lane]      : -1e30f;
            float s1 = v1 ? row[lane + 32] : -1e30f;
            float m = fmaxf(s0, s1);
            #pragma unroll
            for (int off = 16; off > 0; off >>= 1)
                m = fmaxf(m, __shfl_xor_sync(0xffffffffu, m, off));
            float e0 = v0 ? __expf(s0 - m) : 0.0f;
            float e1 = v1 ? __expf(s1 - m) : 0.0f;
            float sum = e0 + e1;
            #pragma unroll
            for (int off = 16; off > 0; off >>= 1)
                sum += __shfl_xor_sync(0xffffffffu, sum, off);
            float inv = 1.0f / sum;
            row[lane]      = e0 * inv;   // exact zeros where masked
            row[lane + 32] = e1 * inv;
        }
    }
    __syncthreads();

    // ---------------- Phase 4: out = P @ V via tf32 MMA ----------------
    // M=64, N=32, K=64 causal-truncated. warp: m-tile i=warp&3, n-tiles jb, jb+2
    {
        const int i  = warp & 3;
        const int m0 = 16 * i;
        const int jb = warp >> 2;

        float acc[2][4];
        #pragma unroll
        for (int t = 0; t < 2; t++)
            #pragma unroll
            for (int e = 0; e < 4; e++) acc[t][e] = 0.0f;

        const int kend = 16 * i + 8;   // probs beyond are exact zeros
        for (int k0 = 0; k0 <= kend; k0 += 8) {
            float a0 = sc[(m0 + gid)     * SCS + k0 + tig];
            float a1 = sc[(m0 + gid + 8) * SCS + k0 + tig];
            float a2 = sc[(m0 + gid)     * SCS + k0 + tig + 4];
            float a3 = sc[(m0 + gid + 8) * SCS + k0 + tig + 4];
            uint32_t h0, l0, h1, l1, h2, l2, h3, l3;
            split_tf(a0, h0, l0); split_tf(a1, h1, l1);
            split_tf(a2, h2, l2); split_tf(a3, h3, l3);
            #pragma unroll
            for (int t = 0; t < 2; t++) {
                int n0 = 8 * (jb + 2 * t);
                uint32_t b0 = vT[(n0 + gid) * VTS + k0 + tig];
                uint32_t b1 = vT[(n0 + gid) * VTS + k0 + tig + 4];
                mma_tf32(acc[t], h0, h1, h2, h3, b0, b1);
                mma_tf32(acc[t], l0, l1, l2, l3, b0, b1);
            }
        }

        float* ob = out + (size_t)b * (TT * HD);
        #pragma unroll
        for (int t = 0; t < 2; t++) {
            int n0 = 8 * (jb + 2 * t);
            int c  = n0 + 2 * tig;
            #pragma unroll
            for (int half = 0; half < 2; half++) {
                int row = m0 + gid + 8 * half;
                *reinterpret_cast<float2*>(ob + row * HD + c) =
                    make_float2(acc[t][2 * half], acc[t][2 * half + 1]);
            }
        }
    }
}

extern "C" void kernel_launch(void* const* d_in, const int* in_sizes, int n_in,
                              void* d_out, int out_size) {
    const float* x  = (const float*)d_in[0];
    const float* Wq = (const float*)d_in[1];
    const float* Wk = (const float*)d_in[2];
    const float* Wv = (const float*)d_in[3];
    float* out = (float*)d_out;

    const int B = in_sizes[0] / (TT * CC);   // 4096
    const size_t smem_bytes = SMEM_FLOATS * sizeof(float);

    static_assert(3 * (SMEM_FLOATS * sizeof(float) + 1024) <= 228 * 1024,
                  "3 CTAs/SM incl. per-CTA reserve");
    cudaFuncSetAttribute(head_attn_kernel,
                         cudaFuncAttributeMaxDynamicSharedMemorySize,
                         (int)smem_bytes);

    head_attn_kernel<<<B, NTHREADS, smem_bytes>>>(x, Wq, Wk, Wv, out);
}

// round 9
// speedup vs baseline: 1.5506x; 1.5506x over previous
#include <cuda_runtime.h>
#include <cstdint>

#define TT 64
#define CC 128
#define HD 32
#define NTHREADS 256

// Bank rules (lane = 4*gid + tig):
//  A loads  arr[(m0+gid)*S + k0+tig]   -> S ≡ 4 (mod 32)
//  B loads  arr[(k0+tig)*S + n0+gid]   -> S ≡ 8 (mod 32)
//  B loads  arr[(n0+gid)*S + k0+tig]   -> S ≡ 4 (mod 32)
#define XSS 132    // x tf32 [64][132]  (A)              extent 128 ✓
#define SCS 68     // scores fp32-bits / probs tf32 [64][68] (A, overlays xs)
#define WSS 104    // W tf32 [128][104] (B, k-major)     extent 96 ✓
#define QSS 36     // q tf32 [64][36]   (A)              extent 32 ✓
#define KSS 36     // k tf32 [64][36]   (B via n-major)  extent 32 ✓
#define VTS 68     // vT tf32 [32][68]  (B via n-major)  extent 64 ✓

#define OFF_XS 0
#define OFF_W  (TT * XSS)                  // 8448
#define OFF_Q  (OFF_W + CC * WSS)          // 21760
#define OFF_K  (OFF_Q + TT * QSS)          // 24064
#define OFF_VT (OFF_K + TT * KSS)          // 26368
#define SMEM_FLOATS (OFF_VT + HD * VTS)    // 28544 words = 114176 B

__device__ __forceinline__ uint32_t f2tf(float f) {
    uint32_t u;
    asm("cvt.rna.tf32.f32 %0, %1;" : "=r"(u) : "f"(f));
    return u;
}
__device__ __forceinline__ void mma_tf32(float c[4],
                                         uint32_t a0, uint32_t a1, uint32_t a2, uint32_t a3,
                                         uint32_t b0, uint32_t b1) {
    asm("mma.sync.aligned.m16n8k8.row.col.f32.tf32.tf32.f32 "
        "{%0,%1,%2,%3},{%4,%5,%6,%7},{%8,%9},{%0,%1,%2,%3};"
        : "+f"(c[0]), "+f"(c[1]), "+f"(c[2]), "+f"(c[3])
        : "r"(a0), "r"(a1), "r"(a2), "r"(a3), "r"(b0), "r"(b1));
}

__global__ __launch_bounds__(NTHREADS, 2)
void head_attn_kernel(const float* __restrict__ x,
                      const float* __restrict__ Wq,
                      const float* __restrict__ Wk,
                      const float* __restrict__ Wv,
                      float* __restrict__ out) {
    extern __shared__ float smem[];
    uint32_t* xu  = reinterpret_cast<uint32_t*>(smem + OFF_XS);  // x tf32
    uint32_t* Wu  = reinterpret_cast<uint32_t*>(smem + OFF_W);   // W tf32
    uint32_t* qu  = reinterpret_cast<uint32_t*>(smem + OFF_Q);   // q tf32 [seq][d]
    uint32_t* ku  = reinterpret_cast<uint32_t*>(smem + OFF_K);   // k tf32 [seq][d]
    uint32_t* vT  = reinterpret_cast<uint32_t*>(smem + OFF_VT);  // vT tf32 [d][seq]
    uint32_t* scb = xu;   // scores (fp32 bits) then probs (tf32 bits), stride SCS

    const int tid  = threadIdx.x;
    const int warp = tid >> 5;
    const int lane = tid & 31;
    const int gid  = lane >> 2;   // 0..7
    const int tig  = lane & 3;    // 0..3
    const int b    = blockIdx.x;
    const float* xb = x + (size_t)b * (TT * CC);

    // ---------------- Phase 0: stage x (tf32) and W (tf32) ----------------
    #pragma unroll
    for (int ii = 0; ii < (TT * CC) / 4 / NTHREADS; ii++) {   // 8
        int i = tid + ii * NTHREADS;
        float4 v4 = reinterpret_cast<const float4*>(xb)[i];
        int idx = i * 4;
        int r = idx >> 7, c = idx & 127;
        *reinterpret_cast<uint4*>(xu + r * XSS + c) =
            make_uint4(f2tf(v4.x), f2tf(v4.y), f2tf(v4.z), f2tf(v4.w));
    }
    #pragma unroll
    for (int ii = 0; ii < (CC * HD) / 4 / NTHREADS; ii++) {   // 4
        int i = tid + ii * NTHREADS;
        int idx = i * 4;
        int d = idx >> 5, c = idx & 31;
        float4 vq = reinterpret_cast<const float4*>(Wq)[i];
        float4 vk = reinterpret_cast<const float4*>(Wk)[i];
        float4 vv = reinterpret_cast<const float4*>(Wv)[i];
        *reinterpret_cast<uint4*>(Wu + d * WSS + c) =
            make_uint4(f2tf(vq.x), f2tf(vq.y), f2tf(vq.z), f2tf(vq.w));
        *reinterpret_cast<uint4*>(Wu + d * WSS + 32 + c) =
            make_uint4(f2tf(vk.x), f2tf(vk.y), f2tf(vk.z), f2tf(vk.w));
        *reinterpret_cast<uint4*>(Wu + d * WSS + 64 + c) =
            make_uint4(f2tf(vv.x), f2tf(vv.y), f2tf(vv.z), f2tf(vv.w));
    }
    __syncthreads();

    // ---------------- Phase 1: QKV via tf32 MMA (no cvt in loop) ----------------
    // M=64, N=96, K=128. warp: m-tile = warp&3, n-tiles = 6*(warp>>2)+0..5
    {
        const int m0    = (warp & 3) * 16;
        const int nbase = (warp >> 2) * 48;

        float acc[6][4];
        #pragma unroll
        for (int j = 0; j < 6; j++)
            #pragma unroll
            for (int t = 0; t < 4; t++) acc[j][t] = 0.0f;

        for (int k0 = 0; k0 < CC; k0 += 8) {
            uint32_t a0 = xu[(m0 + gid)     * XSS + k0 + tig];
            uint32_t a1 = xu[(m0 + gid + 8) * XSS + k0 + tig];
            uint32_t a2 = xu[(m0 + gid)     * XSS + k0 + tig + 4];
            uint32_t a3 = xu[(m0 + gid + 8) * XSS + k0 + tig + 4];
            #pragma unroll
            for (int j = 0; j < 6; j++) {
                int n0 = nbase + 8 * j;
                uint32_t b0 = Wu[(k0 + tig)     * WSS + n0 + gid];
                uint32_t b1 = Wu[(k0 + tig + 4) * WSS + n0 + gid];
                mma_tf32(acc[j], a0, a1, a2, a3, b0, b1);
            }
        }

        // scatter as tf32: n<32 -> q [seq][d]; 32..63 -> k [seq][d]; >=64 -> vT [d][seq]
        #pragma unroll
        for (int j = 0; j < 6; j++) {
            int n0 = nbase + 8 * j;
            int c  = n0 + 2 * tig;
            #pragma unroll
            for (int half = 0; half < 2; half++) {
                int row = m0 + gid + 8 * half;
                uint32_t u0 = f2tf(acc[j][2 * half]);
                uint32_t u1 = f2tf(acc[j][2 * half + 1]);
                if (n0 < 32) {
                    qu[row * QSS + c]     = u0;
                    qu[row * QSS + c + 1] = u1;
                } else if (n0 < 64) {
                    ku[row * KSS + (c - 32)] = u0;
                    ku[row * KSS + (c - 31)] = u1;
                } else {
                    vT[(c - 64) * VTS + row] = u0;
                    vT[(c - 63) * VTS + row] = u1;
                }
            }
        }
    }
    __syncthreads();

    // ---------------- Phase 2: scores via tf32 MMA (zero cvt) ----------------
    // M=64, N=64, K=32. warp: m-tile i=warp&3, n-tiles j=(warp>>2)+2t, j<=2i+1
    {
        const int i  = warp & 3;
        const int m0 = 16 * i;
        const int jb = warp >> 2;
        int jn[4], cnt = 0;
        #pragma unroll
        for (int t = 0; t < 4; t++) {
            int j = jb + 2 * t;
            if (j <= 2 * i + 1) jn[cnt++] = j;
        }

        float acc[4][4];
        #pragma unroll
        for (int t = 0; t < 4; t++)
            #pragma unroll
            for (int e = 0; e < 4; e++) acc[t][e] = 0.0f;

        for (int k0 = 0; k0 < HD; k0 += 8) {
            uint32_t a0 = qu[(m0 + gid)     * QSS + k0 + tig];
            uint32_t a1 = qu[(m0 + gid + 8) * QSS + k0 + tig];
            uint32_t a2 = qu[(m0 + gid)     * QSS + k0 + tig + 4];
            uint32_t a3 = qu[(m0 + gid + 8) * QSS + k0 + tig + 4];
            for (int t = 0; t < cnt; t++) {
                int n0 = 8 * jn[t];
                uint32_t b0 = ku[(n0 + gid) * KSS + k0 + tig];
                uint32_t b1 = ku[(n0 + gid) * KSS + k0 + tig + 4];
                mma_tf32(acc[t], a0, a1, a2, a3, b0, b1);
            }
        }

        const float scale = 0.17677669529663687f;   // 1/sqrt(32)
        for (int t = 0; t < cnt; t++) {
            int n0 = 8 * jn[t];
            int c  = n0 + 2 * tig;
            #pragma unroll
            for (int half = 0; half < 2; half++) {
                int row = m0 + gid + 8 * half;
                scb[row * SCS + c]     = __float_as_uint(acc[t][2 * half]     * scale);
                scb[row * SCS + c + 1] = __float_as_uint(acc[t][2 * half + 1] * scale);
            }
        }
    }
    __syncthreads();

    // ---------------- Phase 3: causal softmax; write probs as tf32 bits ----------------
    {
        for (int r = warp; r < TT; r += 8) {
            uint32_t* row = scb + r * SCS;
            bool v0 = (lane <= r);
            bool v1 = (lane + 32 <= r);
            float s0 = v0 ? __uint_as_float(row[lane])      : -1e30f;
            float s1 = v1 ? __uint_as_float(row[lane + 32]) : -1e30f;
            float m = fmaxf(s0, s1);
            #pragma unroll
            for (int off = 16; off > 0; off >>= 1)
                m = fmaxf(m, __shfl_xor_sync(0xffffffffu, m, off));
            float e0 = v0 ? __expf(s0 - m) : 0.0f;
            float e1 = v1 ? __expf(s1 - m) : 0.0f;
            float sum = e0 + e1;
            #pragma unroll
            for (int off = 16; off > 0; off >>= 1)
                sum += __shfl_xor_sync(0xffffffffu, sum, off);
            float inv = 1.0f / sum;
            row[lane]      = f2tf(e0 * inv);   // tf32(0) = 0 where masked
            row[lane + 32] = f2tf(e1 * inv);
        }
    }
    __syncthreads();

    // ---------------- Phase 4: out = P @ V via tf32 MMA (zero cvt) ----------------
    // M=64, N=32, K=64 causal-truncated. warp: m-tile i=warp&3, n-tiles jb, jb+2
    {
        const int i  = warp & 3;
        const int m0 = 16 * i;
        const int jb = warp >> 2;

        float acc[2][4];
        #pragma unroll
        for (int t = 0; t < 2; t++)
            #pragma unroll
            for (int e = 0; e < 4; e++) acc[t][e] = 0.0f;

        const int kend = 16 * i + 8;   // probs beyond are exact zeros
        for (int k0 = 0; k0 <= kend; k0 += 8) {
            uint32_t a0 = scb[(m0 + gid)     * SCS + k0 + tig];
            uint32_t a1 = scb[(m0 + gid + 8) * SCS + k0 + tig];
            uint32_t a2 = scb[(m0 + gid)     * SCS + k0 + tig + 4];
            uint32_t a3 = scb[(m0 + gid + 8) * SCS + k0 + tig + 4];
            #pragma unroll
            for (int t = 0; t < 2; t++) {
                int n0 = 8 * (jb + 2 * t);
                uint32_t b0 = vT[(n0 + gid) * VTS + k0 + tig];
                uint32_t b1 = vT[(n0 + gid) * VTS + k0 + tig + 4];
                mma_tf32(acc[t], a0, a1, a2, a3, b0, b1);
            }
        }

        float* ob = out + (size_t)b * (TT * HD);
        #pragma unroll
        for (int t = 0; t < 2; t++) {
            int n0 = 8 * (jb + 2 * t);
            int c  = n0 + 2 * tig;
            #pragma unroll
            for (int half = 0; half < 2; half++) {
                int row = m0 + gid + 8 * half;
                *reinterpret_cast<float2*>(ob + row * HD + c) =
                    make_float2(acc[t][2 * half], acc[t][2 * half + 1]);
            }
        }
    }
}

extern "C" void kernel_launch(void* const* d_in, const int* in_sizes, int n_in,
                              void* d_out, int out_size) {
    const float* x  = (const float*)d_in[0];
    const float* Wq = (const float*)d_in[1];
    const float* Wk = (const float*)d_in[2];
    const float* Wv = (const float*)d_in[3];
    float* out = (float*)d_out;

    const int B = in_sizes[0] / (TT * CC);   // 4096
    const size_t smem_bytes = SMEM_FLOATS * sizeof(float);

    static_assert(2 * (SMEM_FLOATS * sizeof(float) + 1024) <= 228 * 1024,
                  "2 CTAs/SM incl. per-CTA reserve");
    cudaFuncSetAttribute(head_attn_kernel,
                         cudaFuncAttributeMaxDynamicSharedMemorySize,
                         (int)smem_bytes);

    head_attn_kernel<<<B, NTHREADS, smem_bytes>>>(x, Wq, Wk, Wv, out);
}

// round 10
// speedup vs baseline: 1.8406x; 1.1870x over previous
#include <cuda_runtime.h>
#include <cstdint>

#define TT 64
#define CC 128
#define HD 32
#define NTHREADS 256

// Bank rules (lane = 4*gid + tig):
//  A loads  arr[(m0+gid)*S + kk+tig]   -> S ≡ 4 (mod 32)
//  B loads  arr[(kk+tig)*S + n0+gid]   -> S ≡ 8 (mod 32)
//  B loads  arr[(n0+gid)*S + kk+tig]   -> S ≡ 4 (mod 32)
#define XHS 68     // x half-tile tf32 [64][68]   (A)  extent 64 ✓
#define WHS 104    // W half-tile tf32 [64][104]  (B)  extent 96 ✓
#define SCS 68     // scores/probs [64][68] (A, overlays staging)
#define QSS 36     // q tf32 [64][36]  (A)             extent 32 ✓
#define KSS 36     // k tf32 [64][36]  (B via n-major) extent 32 ✓
#define VTS 68     // vT tf32 [32][68] (B via n-major) extent 64 ✓

#define OFF_XH 0
#define OFF_WH (TT * XHS)                  // 4352
#define OFF_Q  (OFF_WH + 64 * WHS)         // 11008
#define OFF_K  (OFF_Q + TT * QSS)          // 13312
#define OFF_VT (OFF_K + TT * KSS)          // 15616
#define SMEM_WORDS (OFF_VT + HD * VTS)     // 17792 words = 71168 B

__device__ __forceinline__ uint32_t f2tf(float f) {
    uint32_t u;
    asm("cvt.rna.tf32.f32 %0, %1;" : "=r"(u) : "f"(f));
    return u;
}
__device__ __forceinline__ void mma_tf32(float c[4],
                                         uint32_t a0, uint32_t a1, uint32_t a2, uint32_t a3,
                                         uint32_t b0, uint32_t b1) {
    asm("mma.sync.aligned.m16n8k8.row.col.f32.tf32.tf32.f32 "
        "{%0,%1,%2,%3},{%4,%5,%6,%7},{%8,%9},{%0,%1,%2,%3};"
        : "+f"(c[0]), "+f"(c[1]), "+f"(c[2]), "+f"(c[3])
        : "r"(a0), "r"(a1), "r"(a2), "r"(a3), "r"(b0), "r"(b1));
}

__global__ __launch_bounds__(NTHREADS, 3)
void head_attn_kernel(const float* __restrict__ x,
                      const float* __restrict__ Wq,
                      const float* __restrict__ Wk,
                      const float* __restrict__ Wv,
                      float* __restrict__ out) {
    extern __shared__ float smem[];
    uint32_t* xh  = reinterpret_cast<uint32_t*>(smem + OFF_XH);  // x half tf32
    uint32_t* Wh  = reinterpret_cast<uint32_t*>(smem + OFF_WH);  // W half tf32
    uint32_t* qu  = reinterpret_cast<uint32_t*>(smem + OFF_Q);   // q tf32 [seq][d]
    uint32_t* ku  = reinterpret_cast<uint32_t*>(smem + OFF_K);   // k tf32 [seq][d]
    uint32_t* vT  = reinterpret_cast<uint32_t*>(smem + OFF_VT);  // vT tf32 [d][seq]
    uint32_t* scb = xh;   // scores/probs overlay staging region, stride SCS

    const int tid  = threadIdx.x;
    const int warp = tid >> 5;
    const int lane = tid & 31;
    const int gid  = lane >> 2;   // 0..7
    const int tig  = lane & 3;    // 0..3
    const int b    = blockIdx.x;
    const float* xb = x + (size_t)b * (TT * CC);

    // ---------------- Phase 1: QKV via tf32 MMA with k-split staging ----------------
    // M=64, N=96, K=128 in 2 stages of K=64. warp: m-tile=warp&3, n-tiles=6*(warp>>2)+0..5
    {
        const int m0    = (warp & 3) * 16;
        const int nbase = (warp >> 2) * 48;

        float acc[6][4];
        #pragma unroll
        for (int j = 0; j < 6; j++)
            #pragma unroll
            for (int t = 0; t < 4; t++) acc[j][t] = 0.0f;

        #pragma unroll
        for (int s = 0; s < 2; s++) {
            if (s) __syncthreads();   // stage-0 consumers done before overwrite

            // stage x[:, 64s .. 64s+64) as tf32, [64][68]
            #pragma unroll
            for (int ii = 0; ii < (TT * 64) / 4 / NTHREADS; ii++) {   // 4
                int i = tid + ii * NTHREADS;
                int idx = i * 4;
                int r = idx >> 6, c = idx & 63;
                float4 v4 = *reinterpret_cast<const float4*>(xb + r * CC + 64 * s + c);
                *reinterpret_cast<uint4*>(xh + r * XHS + c) =
                    make_uint4(f2tf(v4.x), f2tf(v4.y), f2tf(v4.z), f2tf(v4.w));
            }
            // stage W[64s .. 64s+64, :] as tf32, [64][104]
            #pragma unroll
            for (int ii = 0; ii < (64 * HD) / 4 / NTHREADS; ii++) {   // 2
                int i = tid + ii * NTHREADS;
                int idx = i * 4;
                int dd = idx >> 5, c = idx & 31;
                int gi = ((64 * s + dd) * HD + c) / 4;
                float4 vq = reinterpret_cast<const float4*>(Wq)[gi];
                float4 vk = reinterpret_cast<const float4*>(Wk)[gi];
                float4 vv = reinterpret_cast<const float4*>(Wv)[gi];
                *reinterpret_cast<uint4*>(Wh + dd * WHS + c) =
                    make_uint4(f2tf(vq.x), f2tf(vq.y), f2tf(vq.z), f2tf(vq.w));
                *reinterpret_cast<uint4*>(Wh + dd * WHS + 32 + c) =
                    make_uint4(f2tf(vk.x), f2tf(vk.y), f2tf(vk.z), f2tf(vk.w));
                *reinterpret_cast<uint4*>(Wh + dd * WHS + 64 + c) =
                    make_uint4(f2tf(vv.x), f2tf(vv.y), f2tf(vv.z), f2tf(vv.w));
            }
            __syncthreads();

            for (int kk = 0; kk < 64; kk += 8) {
                uint32_t a0 = xh[(m0 + gid)     * XHS + kk + tig];
                uint32_t a1 = xh[(m0 + gid + 8) * XHS + kk + tig];
                uint32_t a2 = xh[(m0 + gid)     * XHS + kk + tig + 4];
                uint32_t a3 = xh[(m0 + gid + 8) * XHS + kk + tig + 4];
                #pragma unroll
                for (int j = 0; j < 6; j++) {
                    int n0 = nbase + 8 * j;
                    uint32_t b0 = Wh[(kk + tig)     * WHS + n0 + gid];
                    uint32_t b1 = Wh[(kk + tig + 4) * WHS + n0 + gid];
                    mma_tf32(acc[j], a0, a1, a2, a3, b0, b1);
                }
            }
        }

        // scatter as tf32: n<32 -> q [seq][d]; 32..63 -> k [seq][d]; >=64 -> vT [d][seq]
        #pragma unroll
        for (int j = 0; j < 6; j++) {
            int n0 = nbase + 8 * j;
            int c  = n0 + 2 * tig;
            #pragma unroll
            for (int half = 0; half < 2; half++) {
                int row = m0 + gid + 8 * half;
                uint32_t u0 = f2tf(acc[j][2 * half]);
                uint32_t u1 = f2tf(acc[j][2 * half + 1]);
                if (n0 < 32) {
                    qu[row * QSS + c]     = u0;
                    qu[row * QSS + c + 1] = u1;
                } else if (n0 < 64) {
                    ku[row * KSS + (c - 32)] = u0;
                    ku[row * KSS + (c - 31)] = u1;
                } else {
                    vT[(c - 64) * VTS + row] = u0;
                    vT[(c - 63) * VTS + row] = u1;
                }
            }
        }
    }
    __syncthreads();

    // ---------------- Phase 2: scores via tf32 MMA ----------------
    // M=64, N=64, K=32. warp: m-tile i=warp&3, n-tiles j=(warp>>2)+2t, j<=2i+1
    {
        const int i  = warp & 3;
        const int m0 = 16 * i;
        const int jb = warp >> 2;
        int jn[4], cnt = 0;
        #pragma unroll
        for (int t = 0; t < 4; t++) {
            int j = jb + 2 * t;
            if (j <= 2 * i + 1) jn[cnt++] = j;
        }

        float acc[4][4];
        #pragma unroll
        for (int t = 0; t < 4; t++)
            #pragma unroll
            for (int e = 0; e < 4; e++) acc[t][e] = 0.0f;

        for (int k0 = 0; k0 < HD; k0 += 8) {
            uint32_t a0 = qu[(m0 + gid)     * QSS + k0 + tig];
            uint32_t a1 = qu[(m0 + gid + 8) * QSS + k0 + tig];
            uint32_t a2 = qu[(m0 + gid)     * QSS + k0 + tig + 4];
            uint32_t a3 = qu[(m0 + gid + 8) * QSS + k0 + tig + 4];
            for (int t = 0; t < cnt; t++) {
                int n0 = 8 * jn[t];
                uint32_t b0 = ku[(n0 + gid) * KSS + k0 + tig];
                uint32_t b1 = ku[(n0 + gid) * KSS + k0 + tig + 4];
                mma_tf32(acc[t], a0, a1, a2, a3, b0, b1);
            }
        }

        const float scale = 0.17677669529663687f;   // 1/sqrt(32)
        for (int t = 0; t < cnt; t++) {
            int n0 = 8 * jn[t];
            int c  = n0 + 2 * tig;
            #pragma unroll
            for (int half = 0; half < 2; half++) {
                int row = m0 + gid + 8 * half;
                scb[row * SCS + c]     = __float_as_uint(acc[t][2 * half]     * scale);
                scb[row * SCS + c + 1] = __float_as_uint(acc[t][2 * half + 1] * scale);
            }
        }
    }
    __syncthreads();

    // ---------------- Phase 3: causal softmax; probs written as tf32 bits ----------------
    {
        for (int r = warp; r < TT; r += 8) {
            uint32_t* row = scb + r * SCS;
            bool v0 = (lane <= r);
            bool v1 = (lane + 32 <= r);
            float s0 = v0 ? __uint_as_float(row[lane])      : -1e30f;
            float s1 = v1 ? __uint_as_float(row[lane + 32]) : -1e30f;
            float m = fmaxf(s0, s1);
            #pragma unroll
            for (int off = 16; off > 0; off >>= 1)
                m = fmaxf(m, __shfl_xor_sync(0xffffffffu, m, off));
            float e0 = v0 ? __expf(s0 - m) : 0.0f;
            float e1 = v1 ? __expf(s1 - m) : 0.0f;
            float sum = e0 + e1;
            #pragma unroll
            for (int off = 16; off > 0; off >>= 1)
                sum += __shfl_xor_sync(0xffffffffu, sum, off);
            float inv = 1.0f / sum;
            row[lane]      = f2tf(e0 * inv);   // tf32(0) = 0 where masked
            row[lane + 32] = f2tf(e1 * inv);
        }
    }
    __syncthreads();

    // ---------------- Phase 4: out = P @ V via tf32 MMA ----------------
    // M=64, N=32, K=64 causal-truncated. warp: m-tile i=warp&3, n-tiles jb, jb+2
    {
        const int i  = warp & 3;
        const int m0 = 16 * i;
        const int jb = warp >> 2;

        float acc[2][4];
        #pragma unroll
        for (int t = 0; t < 2; t++)
            #pragma unroll
            for (int e = 0; e < 4; e++) acc[t][e] = 0.0f;

        const int kend = 16 * i + 8;   // probs beyond are exact zeros
        for (int k0 = 0; k0 <= kend; k0 += 8) {
            uint32_t a0 = scb[(m0 + gid)     * SCS + k0 + tig];
            uint32_t a1 = scb[(m0 + gid + 8) * SCS + k0 + tig];
            uint32_t a2 = scb[(m0 + gid)     * SCS + k0 + tig + 4];
            uint32_t a3 = scb[(m0 + gid + 8) * SCS + k0 + tig + 4];
            #pragma unroll
            for (int t = 0; t < 2; t++) {
                int n0 = 8 * (jb + 2 * t);
                uint32_t b0 = vT[(n0 + gid) * VTS + k0 + tig];
                uint32_t b1 = vT[(n0 + gid) * VTS + k0 + tig + 4];
                mma_tf32(acc[t], a0, a1, a2, a3, b0, b1);
            }
        }

        float* ob = out + (size_t)b * (TT * HD);
        #pragma unroll
        for (int t = 0; t < 2; t++) {
            int n0 = 8 * (jb + 2 * t);
            int c  = n0 + 2 * tig;
            #pragma unroll
            for (int half = 0; half < 2; half++) {
                int row = m0 + gid + 8 * half;
                *reinterpret_cast<float2*>(ob + row * HD + c) =
                    make_float2(acc[t][2 * half], acc[t][2 * half + 1]);
            }
        }
    }
}

extern "C" void kernel_launch(void* const* d_in, const int* in_sizes, int n_in,
                              void* d_out, int out_size) {
    const float* x  = (const float*)d_in[0];
    const float* Wq = (const float*)d_in[1];
    const float* Wk = (const float*)d_in[2];
    const float* Wv = (const float*)d_in[3];
    float* out = (float*)d_out;

    const int B = in_sizes[0] / (TT * CC);   // 4096
    const size_t smem_bytes = SMEM_WORDS * sizeof(float);

    static_assert(3 * (SMEM_WORDS * sizeof(float) + 1024) <= 228 * 1024,
                  "3 CTAs/SM incl. per-CTA reserve");
    cudaFuncSetAttribute(head_attn_kernel,
                         cudaFuncAttributeMaxDynamicSharedMemorySize,
                         (int)smem_bytes);

    head_attn_kernel<<<B, NTHREADS, smem_bytes>>>(x, Wq, Wk, Wv, out);
}

// round 11
// speedup vs baseline: 1.9540x; 1.0616x over previous
#include <cuda_runtime.h>
#include <cstdint>

#define TT 64
#define CC 128
#define HD 32
#define NTHREADS 256

// Bank rules (lane = 4*gid + tig):
//  A loads  arr[(m0+gid)*S + kk+tig]   -> S ≡ 4 (mod 32)
//  B loads  arr[(kk+tig)*S + n0+gid]   -> S ≡ 8 (mod 32)
//  B loads  arr[(n0+gid)*S + kk+tig]   -> S ≡ 4 (mod 32)
#define XHS 36     // x quarter-tile tf32 [64][36]  (A)  extent 32 ✓
#define WHS 104    // W quarter-tile tf32 [32][104] (B)  extent 96 ✓
#define SCS 68     // scores/probs [64][68] (A, overlays staging region)
#define QSS 36     // q tf32 [64][36]  (A)             extent 32 ✓
#define KSS 36     // k tf32 [64][36]  (B via n-major) extent 32 ✓
#define VTS 68     // vT tf32 [32][68] (B via n-major) extent 64 ✓

#define OFF_XH 0
#define OFF_WH (TT * XHS)                  // 2304
#define STAGE_WORDS (OFF_WH + 32 * WHS)    // 5632  (sc overlay 64*68=4352 fits)
#define OFF_Q  STAGE_WORDS                 // 5632
#define OFF_K  (OFF_Q + TT * QSS)          // 7936
#define OFF_VT (OFF_K + TT * KSS)          // 10240
#define SMEM_WORDS (OFF_VT + HD * VTS)     // 12416 words = 49664 B

__device__ __forceinline__ uint32_t f2tf(float f) {
    uint32_t u;
    asm("cvt.rna.tf32.f32 %0, %1;" : "=r"(u) : "f"(f));
    return u;
}
__device__ __forceinline__ void mma_tf32(float c[4],
                                         uint32_t a0, uint32_t a1, uint32_t a2, uint32_t a3,
                                         uint32_t b0, uint32_t b1) {
    asm("mma.sync.aligned.m16n8k8.row.col.f32.tf32.tf32.f32 "
        "{%0,%1,%2,%3},{%4,%5,%6,%7},{%8,%9},{%0,%1,%2,%3};"
        : "+f"(c[0]), "+f"(c[1]), "+f"(c[2]), "+f"(c[3])
        : "r"(a0), "r"(a1), "r"(a2), "r"(a3), "r"(b0), "r"(b1));
}

__global__ __launch_bounds__(NTHREADS, 4)
void head_attn_kernel(const float* __restrict__ x,
                      const float* __restrict__ Wq,
                      const float* __restrict__ Wk,
                      const float* __restrict__ Wv,
                      float* __restrict__ out) {
    extern __shared__ float smem[];
    uint32_t* xh  = reinterpret_cast<uint32_t*>(smem + OFF_XH);  // x quarter tf32
    uint32_t* Wh  = reinterpret_cast<uint32_t*>(smem + OFF_WH);  // W quarter tf32
    uint32_t* qu  = reinterpret_cast<uint32_t*>(smem + OFF_Q);   // q tf32 [seq][d]
    uint32_t* ku  = reinterpret_cast<uint32_t*>(smem + OFF_K);   // k tf32 [seq][d]
    uint32_t* vT  = reinterpret_cast<uint32_t*>(smem + OFF_VT);  // vT tf32 [d][seq]
    uint32_t* scb = xh;   // scores/probs overlay staging region, stride SCS

    const int tid  = threadIdx.x;
    const int warp = tid >> 5;
    const int lane = tid & 31;
    const int gid  = lane >> 2;   // 0..7
    const int tig  = lane & 3;    // 0..3
    const int b    = blockIdx.x;
    const float* xb = x + (size_t)b * (TT * CC);

    // ---------------- Phase 1: QKV via tf32 MMA, 4-stage K-quarter staging ----------------
    // M=64, N=96, K=128 in 4 stages of K=32. warp: m-tile=warp&3, n-tiles=6*(warp>>2)+0..5
    {
        const int m0    = (warp & 3) * 16;
        const int nbase = (warp >> 2) * 48;

        float acc[6][4];
        #pragma unroll
        for (int j = 0; j < 6; j++)
            #pragma unroll
            for (int t = 0; t < 4; t++) acc[j][t] = 0.0f;

        #pragma unroll
        for (int s = 0; s < 4; s++) {
            if (s) __syncthreads();   // prior-stage consumers done before overwrite

            // stage x[:, 32s .. 32s+32) as tf32, [64][36]
            #pragma unroll
            for (int ii = 0; ii < (TT * 32) / 4 / NTHREADS; ii++) {   // 2
                int i = tid + ii * NTHREADS;
                int idx = i * 4;
                int r = idx >> 5, c = idx & 31;
                float4 v4 = *reinterpret_cast<const float4*>(xb + r * CC + 32 * s + c);
                *reinterpret_cast<uint4*>(xh + r * XHS + c) =
                    make_uint4(f2tf(v4.x), f2tf(v4.y), f2tf(v4.z), f2tf(v4.w));
            }
            // stage W[32s .. 32s+32, :] as tf32, [32][104]
            {
                int i = tid;                                          // 1 iter
                int idx = i * 4;
                int dd = idx >> 5, c = idx & 31;
                int gi = ((32 * s + dd) * HD + c) / 4;
                float4 vq = reinterpret_cast<const float4*>(Wq)[gi];
                float4 vk = reinterpret_cast<const float4*>(Wk)[gi];
                float4 vv = reinterpret_cast<const float4*>(Wv)[gi];
                *reinterpret_cast<uint4*>(Wh + dd * WHS + c) =
                    make_uint4(f2tf(vq.x), f2tf(vq.y), f2tf(vq.z), f2tf(vq.w));
                *reinterpret_cast<uint4*>(Wh + dd * WHS + 32 + c) =
                    make_uint4(f2tf(vk.x), f2tf(vk.y), f2tf(vk.z), f2tf(vk.w));
                *reinterpret_cast<uint4*>(Wh + dd * WHS + 64 + c) =
                    make_uint4(f2tf(vv.x), f2tf(vv.y), f2tf(vv.z), f2tf(vv.w));
            }
            __syncthreads();

            #pragma unroll
            for (int kk = 0; kk < 32; kk += 8) {
                uint32_t a0 = xh[(m0 + gid)     * XHS + kk + tig];
                uint32_t a1 = xh[(m0 + gid + 8) * XHS + kk + tig];
                uint32_t a2 = xh[(m0 + gid)     * XHS + kk + tig + 4];
                uint32_t a3 = xh[(m0 + gid + 8) * XHS + kk + tig + 4];
                #pragma unroll
                for (int j = 0; j < 6; j++) {
                    int n0 = nbase + 8 * j;
                    uint32_t b0 = Wh[(kk + tig)     * WHS + n0 + gid];
                    uint32_t b1 = Wh[(kk + tig + 4) * WHS + n0 + gid];
                    mma_tf32(acc[j], a0, a1, a2, a3, b0, b1);
                }
            }
        }

        // scatter as tf32: n<32 -> q [seq][d]; 32..63 -> k [seq][d]; >=64 -> vT [d][seq]
        #pragma unroll
        for (int j = 0; j < 6; j++) {
            int n0 = nbase + 8 * j;
            int c  = n0 + 2 * tig;
            #pragma unroll
            for (int half = 0; half < 2; half++) {
                int row = m0 + gid + 8 * half;
                uint32_t u0 = f2tf(acc[j][2 * half]);
                uint32_t u1 = f2tf(acc[j][2 * half + 1]);
                if (n0 < 32) {
                    qu[row * QSS + c]     = u0;
                    qu[row * QSS + c + 1] = u1;
                } else if (n0 < 64) {
                    ku[row * KSS + (c - 32)] = u0;
                    ku[row * KSS + (c - 31)] = u1;
                } else {
                    vT[(c - 64) * VTS + row] = u0;
                    vT[(c - 63) * VTS + row] = u1;
                }
            }
        }
    }
    __syncthreads();

    // ---------------- Phase 2: scores via tf32 MMA ----------------
    // M=64, N=64, K=32. warp: m-tile i=warp&3, n-tiles j=(warp>>2)+2t, j<=2i+1
    {
        const int i  = warp & 3;
        const int m0 = 16 * i;
        const int jb = warp >> 2;
        int jn[4], cnt = 0;
        #pragma unroll
        for (int t = 0; t < 4; t++) {
            int j = jb + 2 * t;
            if (j <= 2 * i + 1) jn[cnt++] = j;
        }

        float acc[4][4];
        #pragma unroll
        for (int t = 0; t < 4; t++)
            #pragma unroll
            for (int e = 0; e < 4; e++) acc[t][e] = 0.0f;

        for (int k0 = 0; k0 < HD; k0 += 8) {
            uint32_t a0 = qu[(m0 + gid)     * QSS + k0 + tig];
            uint32_t a1 = qu[(m0 + gid + 8) * QSS + k0 + tig];
            uint32_t a2 = qu[(m0 + gid)     * QSS + k0 + tig + 4];
            uint32_t a3 = qu[(m0 + gid + 8) * QSS + k0 + tig + 4];
            for (int t = 0; t < cnt; t++) {
                int n0 = 8 * jn[t];
                uint32_t b0 = ku[(n0 + gid) * KSS + k0 + tig];
                uint32_t b1 = ku[(n0 + gid) * KSS + k0 + tig + 4];
                mma_tf32(acc[t], a0, a1, a2, a3, b0, b1);
            }
        }

        const float scale = 0.17677669529663687f;   // 1/sqrt(32)
        for (int t = 0; t < cnt; t++) {
            int n0 = 8 * jn[t];
            int c  = n0 + 2 * tig;
            #pragma unroll
            for (int half = 0; half < 2; half++) {
                int row = m0 + gid + 8 * half;
                scb[row * SCS + c]     = __float_as_uint(acc[t][2 * half]     * scale);
                scb[row * SCS + c + 1] = __float_as_uint(acc[t][2 * half + 1] * scale);
            }
        }
    }
    __syncthreads();

    // ---------------- Phase 3: causal softmax; probs written as tf32 bits ----------------
    {
        for (int r = warp; r < TT; r += 8) {
            uint32_t* row = scb + r * SCS;
            bool v0 = (lane <= r);
            bool v1 = (lane + 32 <= r);
            float s0 = v0 ? __uint_as_float(row[lane])      : -1e30f;
            float s1 = v1 ? __uint_as_float(row[lane + 32]) : -1e30f;
            float m = fmaxf(s0, s1);
            #pragma unroll
            for (int off = 16; off > 0; off >>= 1)
                m = fmaxf(m, __shfl_xor_sync(0xffffffffu, m, off));
            float e0 = v0 ? __expf(s0 - m) : 0.0f;
            float e1 = v1 ? __expf(s1 - m) : 0.0f;
            float sum = e0 + e1;
            #pragma unroll
            for (int off = 16; off > 0; off >>= 1)
                sum += __shfl_xor_sync(0xffffffffu, sum, off);
            float inv = 1.0f / sum;
            row[lane]      = f2tf(e0 * inv);   // tf32(0) = 0 where masked
            row[lane + 32] = f2tf(e1 * inv);
        }
    }
    __syncthreads();

    // ---------------- Phase 4: out = P @ V via tf32 MMA ----------------
    // M=64, N=32, K=64 causal-truncated. warp: m-tile i=warp&3, n-tiles jb, jb+2
    {
        const int i  = warp & 3;
        const int m0 = 16 * i;
        const int jb = warp >> 2;

        float acc[2][4];
        #pragma unroll
        for (int t = 0; t < 2; t++)
            #pragma unroll
            for (int e = 0; e < 4; e++) acc[t][e] = 0.0f;

        const int kend = 16 * i + 8;   // probs beyond are exact zeros
        for (int k0 = 0; k0 <= kend; k0 += 8) {
            uint32_t a0 = scb[(m0 + gid)     * SCS + k0 + tig];
            uint32_t a1 = scb[(m0 + gid + 8) * SCS + k0 + tig];
            uint32_t a2 = scb[(m0 + gid)     * SCS + k0 + tig + 4];
            uint32_t a3 = scb[(m0 + gid + 8) * SCS + k0 + tig + 4];
            #pragma unroll
            for (int t = 0; t < 2; t++) {
                int n0 = 8 * (jb + 2 * t);
                uint32_t b0 = vT[(n0 + gid) * VTS + k0 + tig];
                uint32_t b1 = vT[(n0 + gid) * VTS + k0 + tig + 4];
                mma_tf32(acc[t], a0, a1, a2, a3, b0, b1);
            }
        }

        float* ob = out + (size_t)b * (TT * HD);
        #pragma unroll
        for (int t = 0; t < 2; t++) {
            int n0 = 8 * (jb + 2 * t);
            int c  = n0 + 2 * tig;
            #pragma unroll
            for (int half = 0; half < 2; half++) {
                int row = m0 + gid + 8 * half;
                *reinterpret_cast<float2*>(ob + row * HD + c) =
                    make_float2(acc[t][2 * half], acc[t][2 * half + 1]);
            }
        }
    }
}

extern "C" void kernel_launch(void* const* d_in, const int* in_sizes, int n_in,
                              void* d_out, int out_size) {
    const float* x  = (const float*)d_in[0];
    const float* Wq = (const float*)d_in[1];
    const float* Wk = (const float*)d_in[2];
    const float* Wv = (const float*)d_in[3];
    float* out = (float*)d_out;

    const int B = in_sizes[0] / (TT * CC);   // 4096
    const size_t smem_bytes = SMEM_WORDS * sizeof(float);

    static_assert(4 * (SMEM_WORDS * sizeof(float) + 1024) <= 228 * 1024,
                  "4 CTAs/SM incl. per-CTA reserve");
    cudaFuncSetAttribute(head_attn_kernel,
                         cudaFuncAttributeMaxDynamicSharedMemorySize,
                         (int)smem_bytes);

    head_attn_kernel<<<B, NTHREADS, smem_bytes>>>(x, Wq, Wk, Wv, out);
}